// round 15
// baseline (speedup 1.0000x reference)
#include <cuda_runtime.h>
#include <cuda_fp16.h>
#include <cstdint>

#define BATCH 4
#define EMB   256
#define NTOK  4096
#define TCK   128
#define NITER (NTOK / TCK)
#define LOG2E 1.4426950408889634f

__device__ __half g_q [(size_t)BATCH * NTOK * EMB];
__device__ __half g_k [(size_t)BATCH * NTOK * EMB];
__device__ __half g_vt[(size_t)BATCH * EMB * NTOK];

#if defined(__CUDA_ARCH_FEAT_SM103_ALL) || defined(__CUDA_ARCH_FEAT_SM100_ALL) || \
    defined(__CUDA_ARCH_FEAT_SM101_ALL) || defined(__CUDA_ARCH_SPECIFIC__)
#define TC_OK 1
#else
#define TC_OK 0
#endif

#if TC_OK
__device__ __forceinline__ uint32_t smem_u32(const void* p) {
    uint32_t a;
    asm("{ .reg .u64 t; cvta.to.shared.u64 t, %1; cvt.u32.u64 %0, t; }"
        : "=r"(a) : "l"(p));
    return a;
}
__device__ __forceinline__ uint32_t elect_one() {
    uint32_t pred;
    asm volatile("{\n\t.reg .pred p;\n\telect.sync _|p, 0xFFFFFFFF;\n\t"
                 "selp.b32 %0, 1, 0, p;\n\t}" : "=r"(pred));
    return pred;
}
__device__ __forceinline__ float f2tf32(float f) {
    uint32_t u;
    asm("cvt.rna.tf32.f32 %0, %1;" : "=r"(u) : "f"(f));
    return __uint_as_float(u);
}

#define MBAR_INIT(mbar, cnt) \
    asm volatile("mbarrier.init.shared.b64 [%0], %1;" :: "r"(mbar), "r"(cnt) : "memory")
#define MBAR_INVAL(mbar) \
    asm volatile("mbarrier.inval.shared.b64 [%0];" :: "r"(mbar) : "memory")
#define MBAR_WAIT(mbar, parity) do {                                             \
    uint32_t _mb = (mbar); uint32_t _ph = (parity); uint32_t _done;              \
    asm volatile("{\n\t.reg .pred p;\n\t"                                        \
        "mbarrier.try_wait.parity.acquire.cta.shared::cta.b64 p, [%1], %2;\n\t"  \
        "selp.b32 %0, 1, 0, p;\n\t}"                                             \
        : "=r"(_done) : "r"(_mb), "r"(_ph) : "memory");                          \
    if (!_done) {                                                                \
        asm volatile("{\n\t.reg .pred P1;\n\t"                                   \
            "WL_%=:\n\t"                                                         \
            "mbarrier.try_wait.parity.acquire.cta.shared::cta.b64 P1, [%0], %1, 0x989680;\n\t" \
            "@P1 bra.uni WD_%=;\n\t"                                             \
            "bra.uni WL_%=;\n\t"                                                 \
            "WD_%=:\n\t}" :: "r"(_mb), "r"(_ph) : "memory");                     \
    }                                                                            \
} while (0)

#define TC_ALLOC(dst_smem, ncols) \
    asm volatile("tcgen05.alloc.cta_group::1.sync.aligned.shared::cta.b32 [%0], %1;" \
                 :: "r"(dst_smem), "r"(ncols) : "memory")
#define TC_RELINQ() \
    asm volatile("tcgen05.relinquish_alloc_permit.cta_group::1.sync.aligned;")
#define TC_DEALLOC(tmem, ncols) \
    asm volatile("tcgen05.dealloc.cta_group::1.sync.aligned.b32 %0, %1;" \
                 :: "r"(tmem), "r"(ncols))
#define TC_COMMIT(mbar) \
    asm volatile("tcgen05.commit.cta_group::1.mbarrier::arrive::one.shared::cluster.b64 [%0];" \
                 :: "r"(mbar) : "memory")
#define TC_WAIT_LD()  asm volatile("tcgen05.wait::ld.sync.aligned;"  ::: "memory")
#define TC_WAIT_ST()  asm volatile("tcgen05.wait::st.sync.aligned;"  ::: "memory")
#define TC_FENCE_BEFORE() asm volatile("tcgen05.fence::before_thread_sync;" ::: "memory")
#define TC_FENCE_AFTER()  asm volatile("tcgen05.fence::after_thread_sync;"  ::: "memory")
#define FENCE_ASYNC_SHARED() asm volatile("fence.proxy.async.shared::cta;" ::: "memory")

#define CP_ASYNC16(dst, src) \
    asm volatile("cp.async.ca.shared.global [%0], [%1], 16;" \
                 :: "r"(dst), "l"(src) : "memory")
#define CP_COMMIT() asm volatile("cp.async.commit_group;" ::: "memory")
#define CP_WAIT0()  asm volatile("cp.async.wait_group 0;" ::: "memory")

#define LDTM_X32(r, addr) \
    asm volatile("tcgen05.ld.sync.aligned.32x32b.x32.b32 " \
        "{%0, %1, %2, %3, %4, %5, %6, %7, %8, %9, %10, %11, %12, %13, %14, %15, " \
        " %16, %17, %18, %19, %20, %21, %22, %23, %24, %25, %26, %27, %28, %29, %30, %31}, [%32];" \
        : "=r"((r)[0]),  "=r"((r)[1]),  "=r"((r)[2]),  "=r"((r)[3]),  \
          "=r"((r)[4]),  "=r"((r)[5]),  "=r"((r)[6]),  "=r"((r)[7]),  \
          "=r"((r)[8]),  "=r"((r)[9]),  "=r"((r)[10]), "=r"((r)[11]), \
          "=r"((r)[12]), "=r"((r)[13]), "=r"((r)[14]), "=r"((r)[15]), \
          "=r"((r)[16]), "=r"((r)[17]), "=r"((r)[18]), "=r"((r)[19]), \
          "=r"((r)[20]), "=r"((r)[21]), "=r"((r)[22]), "=r"((r)[23]), \
          "=r"((r)[24]), "=r"((r)[25]), "=r"((r)[26]), "=r"((r)[27]), \
          "=r"((r)[28]), "=r"((r)[29]), "=r"((r)[30]), "=r"((r)[31]) \
        : "r"(addr))

#define STTM_X16(addr, r) \
    asm volatile("tcgen05.st.sync.aligned.32x32b.x16.b32 [%0], " \
        "{%1, %2, %3, %4, %5, %6, %7, %8, %9, %10, %11, %12, %13, %14, %15, %16};" \
        :: "r"(addr), \
           "r"((r)[0]),  "r"((r)[1]),  "r"((r)[2]),  "r"((r)[3]),  \
           "r"((r)[4]),  "r"((r)[5]),  "r"((r)[6]),  "r"((r)[7]),  \
           "r"((r)[8]),  "r"((r)[9]),  "r"((r)[10]), "r"((r)[11]), \
           "r"((r)[12]), "r"((r)[13]), "r"((r)[14]), "r"((r)[15]) \
        : "memory")

__device__ __forceinline__ uint64_t make_desc(uint32_t smem_addr) {
    return 0x4000404000010000ULL | ((uint64_t)(smem_addr >> 4) & 0x3FFF);
}
__device__ __forceinline__ void mma_tf32_ss(uint32_t d, uint64_t a, uint64_t b,
                                            uint32_t idesc, uint32_t en) {
    asm volatile("{\n\t.reg .pred p;\n\tsetp.ne.u32 p, %5, 0;\n\t"
        "tcgen05.mma.cta_group::1.kind::tf32 [%0], %1, %2, %3, {%4, %4, %4, %4}, p;\n\t}"
        :: "r"(d), "l"(a), "l"(b), "r"(idesc), "r"(0u), "r"(en) : "memory");
}
__device__ __forceinline__ void mma_f16_ss(uint32_t d, uint64_t a, uint64_t b,
                                           uint32_t idesc, uint32_t en) {
    asm volatile("{\n\t.reg .pred p;\n\tsetp.ne.u32 p, %5, 0;\n\t"
        "tcgen05.mma.cta_group::1.kind::f16 [%0], %1, %2, %3, {%4, %4, %4, %4}, p;\n\t}"
        :: "r"(d), "l"(a), "l"(b), "r"(idesc), "r"(0u), "r"(en) : "memory");
}
__device__ __forceinline__ void mma_f16_ts(uint32_t d, uint32_t a, uint64_t b,
                                           uint32_t idesc, uint32_t en) {
    asm volatile("{\n\t.reg .pred p;\n\tsetp.ne.u32 p, %5, 0;\n\t"
        "tcgen05.mma.cta_group::1.kind::f16 [%0], [%1], %2, %3, {%4, %4, %4, %4}, p;\n\t}"
        :: "r"(d), "r"(a), "l"(b), "r"(idesc), "r"(0u), "r"(en) : "memory");
}
__device__ __forceinline__ uint32_t sw128(uint32_t b) { return b ^ ((b >> 3) & 0x70); }
#endif  // TC_OK

// ============================================================================
// tcgen05 QKV projection (UNCHANGED from R14 pass; fp16 outputs).
// ============================================================================
#define PSM_X   0
#define PSM_W   131072
#define PSM_PTR 196608
#define PSM_MB  196616
#define PROJ_SMEM 196640
#define IDESC_P ((1u << 4) | (2u << 7) | (2u << 10) | (4u << 17) | (8u << 24))

__global__ __launch_bounds__(256, 1) void proj_tc_kernel(
    const float* __restrict__ x,
    const float* __restrict__ Wq, const float* __restrict__ bq,
    const float* __restrict__ Wk, const float* __restrict__ bk,
    const float* __restrict__ Wv, const float* __restrict__ bv)
{
#if TC_OK
    extern __shared__ char sm[];
    const uint32_t smb = smem_u32(sm);
    const int tid = threadIdx.x;
    const int wid = tid >> 5;
    const int sp  = wid & 3;
    const int wg  = wid >> 2;
    const int lid = tid & 31;
    const int n0  = blockIdx.x * 128;
    const int b   = blockIdx.y;

    if (wid == 0) {
        TC_ALLOC(smb + PSM_PTR, 512);
        TC_RELINQ();
        if (elect_one()) {
            MBAR_INIT(smb + PSM_MB + 0, 1);
            MBAR_INIT(smb + PSM_MB + 8, 1);
        }
    }
    __syncthreads();
    uint32_t tmem;
    asm volatile("ld.shared.b32 %0, [%1];" : "=r"(tmem) : "r"(smb + PSM_PTR));
    const uint32_t woff = (uint32_t)sp << 21;
    const int n = sp * 32 + lid;

    {
        const float* xb = x + (size_t)b * EMB * NTOK + n0;
        #pragma unroll 8
        for (int it = 0; it < 32; ++it) {
            const int idx = tid + it * 256;
            const int c   = idx >> 5;
            const int nc4 = idx & 31;
            float4 v = *(const float4*)&xb[(size_t)c * NTOK + nc4 * 4];
            const uint32_t cb = (uint32_t)((c >> 5) * 16384 + ((c >> 2) & 7) * 16 + (c & 3) * 4);
            #pragma unroll
            for (int k2 = 0; k2 < 4; ++k2) {
                const int nn = nc4 * 4 + k2;
                uint32_t byte = cb + (uint32_t)((nn >> 3) * 1024 + (nn & 7) * 128);
                *(float*)(sm + PSM_X + sw128(byte)) =
                    f2tf32(k2 == 0 ? v.x : k2 == 1 ? v.y : k2 == 2 ? v.z : v.w);
            }
        }
    }

    const uint64_t xdesc = make_desc(smb + PSM_X);
    const float* Ws[3] = { Wq, Wk, Wv };
    int php[2] = { 0, 0 };

    for (int i = 0; i < 24; ++i) {
        const int bi = i & 1;
        if (i >= 2) { MBAR_WAIT(smb + PSM_MB + bi * 8, php[bi]); php[bi] ^= 1; }

        if (i == 16) {
            TC_FENCE_AFTER();
            const float scl = 0.0625f * LOG2E;
            __half* dst0 = g_q + ((size_t)b * NTOK + n0 + n) * EMB;
            #pragma unroll
            for (int cc = 0; cc < 4; ++cc) {
                const int col0 = wg * 128 + cc * 32;
                uint32_t r[32];
                LDTM_X32(r, tmem + (uint32_t)col0 + woff);
                TC_WAIT_LD();
                #pragma unroll
                for (int j = 0; j < 32; j += 8) {
                    uint32_t w[4];
                    #pragma unroll
                    for (int k2 = 0; k2 < 4; ++k2) {
                        const float v0 = (__uint_as_float(r[j+2*k2+0]) + __ldg(&bq[col0+j+2*k2+0])) * scl;
                        const float v1 = (__uint_as_float(r[j+2*k2+1]) + __ldg(&bq[col0+j+2*k2+1])) * scl;
                        asm("cvt.rn.f16x2.f32 %0, %1, %2;" : "=r"(w[k2]) : "f"(v1), "f"(v0));
                    }
                    uint4 o; o.x = w[0]; o.y = w[1]; o.z = w[2]; o.w = w[3];
                    *(uint4*)&dst0[col0 + j] = o;
                }
            }
            TC_FENCE_BEFORE();
            __syncthreads();
        }

        {
            const float* W = Ws[i >> 3] + (size_t)((i & 7) * 32) * EMB;
            char* buf = sm + PSM_W + bi * 32768;
            #pragma unroll
            for (int it = 0; it < 8; ++it) {
                const int idx = tid + it * 256;
                const int r  = idx >> 6;
                const int c4 = idx & 63;
                float4 v = *(const float4*)&W[(size_t)r * EMB + c4 * 4];
                v.x = f2tf32(v.x); v.y = f2tf32(v.y);
                v.z = f2tf32(v.z); v.w = f2tf32(v.w);
                uint32_t byte = (uint32_t)(((r >> 3) + (c4 >> 3) * 4) * 1024
                                           + (r & 7) * 128 + (c4 & 7) * 16);
                *(float4*)(buf + sw128(byte)) = v;
            }
        }
        FENCE_ASYNC_SHARED();
        __syncthreads();

        if (wid == 0) {
            TC_FENCE_AFTER();
            if (elect_one()) {
                const uint64_t wd = make_desc(smb + PSM_W + (uint32_t)(bi * 32768));
                const uint32_t dtm = tmem + (uint32_t)(((i >> 3) == 1 ? 256 : 0) + (i & 7) * 32);
                #pragma unroll
                for (int s = 0; s < 32; ++s) {
                    mma_tf32_ss(dtm, xdesc + (uint64_t)((s >> 2) * 1024 + (s & 3) * 2),
                                     wd    + (uint64_t)((s >> 2) * 256  + (s & 3) * 2),
                                IDESC_P, (uint32_t)(s > 0));
                }
                TC_COMMIT(smb + PSM_MB + bi * 8);
            }
        }
    }
    MBAR_WAIT(smb + PSM_MB + 0, php[0]); php[0] ^= 1;
    MBAR_WAIT(smb + PSM_MB + 8, php[1]); php[1] ^= 1;
    TC_FENCE_AFTER();

    {
        __half* dst = g_k + ((size_t)b * NTOK + n0 + n) * EMB;
        #pragma unroll
        for (int cc = 0; cc < 4; ++cc) {
            const int col0 = wg * 128 + cc * 32;
            uint32_t r[32];
            LDTM_X32(r, tmem + (uint32_t)(256 + col0) + woff);
            TC_WAIT_LD();
            #pragma unroll
            for (int j = 0; j < 32; j += 8) {
                uint32_t w[4];
                #pragma unroll
                for (int k2 = 0; k2 < 4; ++k2) {
                    const float v0 = __uint_as_float(r[j+2*k2+0]) + __ldg(&bk[col0+j+2*k2+0]);
                    const float v1 = __uint_as_float(r[j+2*k2+1]) + __ldg(&bk[col0+j+2*k2+1]);
                    asm("cvt.rn.f16x2.f32 %0, %1, %2;" : "=r"(w[k2]) : "f"(v1), "f"(v0));
                }
                uint4 o; o.x = w[0]; o.y = w[1]; o.z = w[2]; o.w = w[3];
                *(uint4*)&dst[col0 + j] = o;
            }
        }
    }
    {
        __half* vt = g_vt + (size_t)b * EMB * NTOK + n0 + n;
        #pragma unroll
        for (int cc = 0; cc < 4; ++cc) {
            const int col0 = wg * 128 + cc * 32;
            uint32_t r[32];
            LDTM_X32(r, tmem + (uint32_t)col0 + woff);
            TC_WAIT_LD();
            #pragma unroll
            for (int j = 0; j < 32; ++j) {
                const float v = __uint_as_float(r[j]) + __ldg(&bv[col0 + j]);
                vt[(size_t)(col0 + j) * NTOK] = __float2half(v);
            }
        }
    }
    __syncthreads();
    if (wid == 0) {
        if (elect_one()) { MBAR_INVAL(smb + PSM_MB + 0); MBAR_INVAL(smb + PSM_MB + 8); }
        TC_DEALLOC(tmem, 512);
    }
#endif
}

// ============================================================================
// fp16 tcgen05 attention v6: mb2-wait hoisted to top; K(n+1)+V(n) prefetched
// together under the LDTM window; 2 syncs/iter.
// CTA = (128 q, batch), 512 threads. SMEM: Q 64K + K 64K + V 64K.
// TMEM: S@0 (128 fp32), P0@128, P1@192 (f16x2), O@256 (256 fp32).
// ============================================================================
#define SM_Q   0
#define SM_K   65536
#define SM_V   131072
#define SM_PTR 196608
#define SM_M1  196616
#define SM_M2  196624
#define SM_L   196640
#define ATT_SMEM (196640 + 4 * 128 * 4)
#define TM_S 0
#define TM_P 128
#define TM_O 256
#define IDESC1 ((1u << 4) | (16u << 17) | (8u << 24))
#define IDESC2 ((1u << 4) | (32u << 17) | (8u << 24))

#if TC_OK
__device__ __forceinline__ void load_qk_tile(char* dst, const __half* g, int tid) {
    #pragma unroll 8
    for (int it = 0; it < 8; ++it) {
        const int idx = tid + it * 512;
        const int r = idx >> 5;
        const int c = idx & 31;
        uint4 v = *(const uint4*)&g[(size_t)r * EMB + c * 8];
        uint32_t byte = (uint32_t)(((r >> 3) + (c >> 3) * 16) * 1024
                                   + (r & 7) * 128 + (c & 7) * 16);
        *(uint4*)(dst + sw128(byte)) = v;
    }
}
__device__ __forceinline__ void cp_k_tile(uint32_t dst, const __half* g, int tid) {
    #pragma unroll
    for (int it = 0; it < 8; ++it) {
        const int idx = tid + it * 512;
        const int r = idx >> 5;
        const int c = idx & 31;
        uint32_t byte = (uint32_t)(((r >> 3) + (c >> 3) * 16) * 1024
                                   + (r & 7) * 128 + (c & 7) * 16);
        CP_ASYNC16(dst + sw128(byte), (const char*)(g + (size_t)r * EMB + c * 8));
    }
}
__device__ __forceinline__ void cp_v_tile(uint32_t dst, const __half* g, int tid) {
    #pragma unroll
    for (int it = 0; it < 8; ++it) {
        const int idx = tid + it * 512;
        const int r = idx >> 4;
        const int c = idx & 15;
        uint32_t byte = (uint32_t)(((r >> 3) + (c >> 3) * 32) * 1024
                                   + (r & 7) * 128 + (c & 7) * 16);
        CP_ASYNC16(dst + sw128(byte), (const char*)(g + (size_t)r * NTOK + c * 8));
    }
}
__device__ __forceinline__ void issue_mma1(uint32_t sdst, uint64_t qdesc,
                                           uint64_t kdesc, uint32_t mbar) {
    #pragma unroll
    for (int s = 0; s < 16; ++s) {
        mma_f16_ss(sdst, qdesc + (uint64_t)((s >> 2) * 1024 + (s & 3) * 2),
                         kdesc + (uint64_t)((s >> 2) * 1024 + (s & 3) * 2),
                   IDESC1, (uint32_t)(s > 0));
    }
    TC_COMMIT(mbar);
}
#endif

__global__ __launch_bounds__(512, 1) void attn_tc_kernel(float* __restrict__ out)
{
#if TC_OK
    extern __shared__ char sm[];
    const uint32_t smb = smem_u32(sm);
    const int tid = threadIdx.x;
    const int wid = tid >> 5;
    const int sp  = wid & 3;
    const int wg  = wid >> 2;
    const int lid = tid & 31;
    const int q0  = blockIdx.x * 128;
    const int b   = blockIdx.y;

    if (wid == 0) {
        TC_ALLOC(smb + SM_PTR, 512);
        TC_RELINQ();
        if (elect_one()) { MBAR_INIT(smb + SM_M1, 1); MBAR_INIT(smb + SM_M2, 1); }
    }
    __syncthreads();
    uint32_t tmem;
    asm volatile("ld.shared.b32 %0, [%1];" : "=r"(tmem) : "r"(smb + SM_PTR));
    const uint32_t woff = (uint32_t)sp << 21;

    const uint64_t qdesc = make_desc(smb + SM_Q);
    const uint64_t kdesc = make_desc(smb + SM_K);
    const uint64_t vdesc = make_desc(smb + SM_V);

    const __half* gk = g_k + (size_t)b * NTOK * EMB;
    const __half* gv = g_vt + (size_t)b * EMB * NTOK;

    load_qk_tile(sm + SM_Q, g_q + ((size_t)b * NTOK + q0) * EMB, tid);
    load_qk_tile(sm + SM_K, gk, tid);
    FENCE_ASYNC_SHARED();
    __syncthreads();
    if (wid == 0) {
        TC_FENCE_AFTER();
        if (elect_one()) issue_mma1(tmem + TM_S, qdesc, kdesc, smb + SM_M1);
    }

    float lsum = 0.f;
    int ph1 = 0, ph2 = 0;

    for (int itn = 0; itn < NITER; ++itn) {
        const int k0 = itn * TCK;
        const uint32_t pbuf = TM_P + (uint32_t)((itn & 1) << 6);

        // (1) wait MMA1(n): S ready, K buffer free
        MBAR_WAIT(smb + SM_M1, ph1); ph1 ^= 1;
        // (2) wait MMA2(n-1): V buffer + P(n-1) free (usually already done)
        if (itn > 0) { MBAR_WAIT(smb + SM_M2, ph2); ph2 ^= 1; }
        TC_FENCE_AFTER();

        // (3) prefetch K(n+1) AND V(n) in one group (overlap LDTM below)
        if (itn < NITER - 1) cp_k_tile(smb + SM_K, gk + (size_t)(k0 + TCK) * EMB, tid);
        cp_v_tile(smb + SM_V, gv + k0, tid);
        CP_COMMIT();

        // (4) read S (frees S region)
        uint32_t sreg[32];
        LDTM_X32(sreg, tmem + TM_S + (uint32_t)(wg << 5) + woff);
        TC_WAIT_LD();

        // (5) loads landed + S read by all -> issue MMA1(n+1)
        CP_WAIT0();
        FENCE_ASYNC_SHARED();
        __syncthreads();
        if (itn < NITER - 1 && wid == 0) {
            TC_FENCE_AFTER();
            if (elect_one()) issue_mma1(tmem + TM_S, qdesc, kdesc, smb + SM_M1);
        }

        // (6) softmax + pack; store P[n&1]
        {
            uint32_t pr[16];
            float part = 0.f;
            #pragma unroll
            for (int j = 0; j < 16; ++j) {
                uint32_t h2;
                asm("cvt.rn.f16x2.f32 %0, %1, %2;" : "=r"(h2)
                    : "f"(__uint_as_float(sreg[2 * j + 1])),
                      "f"(__uint_as_float(sreg[2 * j])));
                asm("ex2.approx.f16x2 %0, %1;" : "=r"(pr[j]) : "r"(h2));
                const float2 f = __half22float2(*(__half2*)&pr[j]);
                part += f.x + f.y;
            }
            lsum += part;
            STTM_X16(tmem + pbuf + (uint32_t)(wg << 4) + woff, pr);
            TC_WAIT_ST();
        }
        TC_FENCE_BEFORE();

        // (7) all STTM done -> issue MMA2(n)
        __syncthreads();
        if (wid == 0) {
            TC_FENCE_AFTER();
            if (elect_one()) {
                #pragma unroll
                for (int s = 0; s < 8; ++s) {
                    mma_f16_ts(tmem + TM_O, tmem + pbuf + s * 8,
                               vdesc + (uint64_t)((s >> 2) * 2048 + (s & 3) * 2),
                               IDESC2, (uint32_t)((itn > 0) | (s > 0)));
                }
                TC_COMMIT(smb + SM_M2);
            }
        }
    }

    // epilogue
    MBAR_WAIT(smb + SM_M2, ph2); ph2 ^= 1;
    TC_FENCE_AFTER();
    {
        float* lpart = (float*)(sm + SM_L);
        const int row = sp * 32 + lid;
        lpart[wg * 128 + row] = lsum;
        __syncthreads();
        const float inv = 1.f / (lpart[row] + lpart[128 + row]
                               + lpart[256 + row] + lpart[384 + row]);

        float* ob = out + ((size_t)b * NTOK + q0 + row) * EMB + wg * 64;
        #pragma unroll
        for (int ch = 0; ch < 2; ++ch) {
            uint32_t r[32];
            LDTM_X32(r, tmem + TM_O + (uint32_t)(wg * 64 + ch * 32) + woff);
            TC_WAIT_LD();
            #pragma unroll
            for (int j = 0; j < 32; j += 4) {
                float4 o;
                o.x = __uint_as_float(r[j + 0]) * inv;
                o.y = __uint_as_float(r[j + 1]) * inv;
                o.z = __uint_as_float(r[j + 2]) * inv;
                o.w = __uint_as_float(r[j + 3]) * inv;
                *(float4*)&ob[ch * 32 + j] = o;
            }
        }
    }
    __syncthreads();
    if (wid == 0) {
        if (elect_one()) { MBAR_INVAL(smb + SM_M1); MBAR_INVAL(smb + SM_M2); }
        TC_DEALLOC(tmem, 512);
    }
#endif
}

// ---------------------------------------------------------------------------
extern "C" void kernel_launch(void* const* d_in, const int* in_sizes, int n_in,
                              void* d_out, int out_size)
{
    const float* x  = (const float*)d_in[0];
    const float* Wq = (const float*)d_in[1];
    const float* bq = (const float*)d_in[2];
    const float* Wk = (const float*)d_in[3];
    const float* bk = (const float*)d_in[4];
    const float* Wv = (const float*)d_in[5];
    const float* bv = (const float*)d_in[6];
    float* out = (float*)d_out;

    cudaFuncSetAttribute(proj_tc_kernel,
                         cudaFuncAttributeMaxDynamicSharedMemorySize, PROJ_SMEM);
    cudaFuncSetAttribute(attn_tc_kernel,
                         cudaFuncAttributeMaxDynamicSharedMemorySize, ATT_SMEM);

    dim3 gproj(NTOK / 128, BATCH);
    proj_tc_kernel<<<gproj, 256, PROJ_SMEM>>>(x, Wq, bq, Wk, bk, Wv, bv);

    dim3 gatt(NTOK / 128, BATCH);
    attn_tc_kernel<<<gatt, 512, ATT_SMEM>>>(out);
}

// round 16
// speedup vs baseline: 1.1357x; 1.1357x over previous
#include <cuda_runtime.h>
#include <cuda_fp16.h>
#include <cstdint>

#define BATCH 4
#define EMB   256
#define NTOK  4096
#define TCK   128
#define NITER (NTOK / TCK)
#define LOG2E 1.4426950408889634f

__device__ __half g_q [(size_t)BATCH * NTOK * EMB];
__device__ __half g_k [(size_t)BATCH * NTOK * EMB];
__device__ __half g_vt[(size_t)BATCH * EMB * NTOK];

#if defined(__CUDA_ARCH_FEAT_SM103_ALL) || defined(__CUDA_ARCH_FEAT_SM100_ALL) || \
    defined(__CUDA_ARCH_FEAT_SM101_ALL) || defined(__CUDA_ARCH_SPECIFIC__)
#define TC_OK 1
#else
#define TC_OK 0
#endif

#if TC_OK
__device__ __forceinline__ uint32_t smem_u32(const void* p) {
    uint32_t a;
    asm("{ .reg .u64 t; cvta.to.shared.u64 t, %1; cvt.u32.u64 %0, t; }"
        : "=r"(a) : "l"(p));
    return a;
}
__device__ __forceinline__ uint32_t elect_one() {
    uint32_t pred;
    asm volatile("{\n\t.reg .pred p;\n\telect.sync _|p, 0xFFFFFFFF;\n\t"
                 "selp.b32 %0, 1, 0, p;\n\t}" : "=r"(pred));
    return pred;
}
__device__ __forceinline__ float f2tf32(float f) {
    uint32_t u;
    asm("cvt.rna.tf32.f32 %0, %1;" : "=r"(u) : "f"(f));
    return __uint_as_float(u);
}

#define MBAR_INIT(mbar, cnt) \
    asm volatile("mbarrier.init.shared.b64 [%0], %1;" :: "r"(mbar), "r"(cnt) : "memory")
#define MBAR_INVAL(mbar) \
    asm volatile("mbarrier.inval.shared.b64 [%0];" :: "r"(mbar) : "memory")
#define MBAR_WAIT(mbar, parity) do {                                             \
    uint32_t _mb = (mbar); uint32_t _ph = (parity); uint32_t _done;              \
    asm volatile("{\n\t.reg .pred p;\n\t"                                        \
        "mbarrier.try_wait.parity.acquire.cta.shared::cta.b64 p, [%1], %2;\n\t"  \
        "selp.b32 %0, 1, 0, p;\n\t}"                                             \
        : "=r"(_done) : "r"(_mb), "r"(_ph) : "memory");                          \
    if (!_done) {                                                                \
        asm volatile("{\n\t.reg .pred P1;\n\t"                                   \
            "WL_%=:\n\t"                                                         \
            "mbarrier.try_wait.parity.acquire.cta.shared::cta.b64 P1, [%0], %1, 0x989680;\n\t" \
            "@P1 bra.uni WD_%=;\n\t"                                             \
            "bra.uni WL_%=;\n\t"                                                 \
            "WD_%=:\n\t}" :: "r"(_mb), "r"(_ph) : "memory");                     \
    }                                                                            \
} while (0)

#define TC_ALLOC(dst_smem, ncols) \
    asm volatile("tcgen05.alloc.cta_group::1.sync.aligned.shared::cta.b32 [%0], %1;" \
                 :: "r"(dst_smem), "r"(ncols) : "memory")
#define TC_RELINQ() \
    asm volatile("tcgen05.relinquish_alloc_permit.cta_group::1.sync.aligned;")
#define TC_DEALLOC(tmem, ncols) \
    asm volatile("tcgen05.dealloc.cta_group::1.sync.aligned.b32 %0, %1;" \
                 :: "r"(tmem), "r"(ncols))
#define TC_COMMIT(mbar) \
    asm volatile("tcgen05.commit.cta_group::1.mbarrier::arrive::one.shared::cluster.b64 [%0];" \
                 :: "r"(mbar) : "memory")
#define TC_WAIT_LD()  asm volatile("tcgen05.wait::ld.sync.aligned;"  ::: "memory")
#define TC_WAIT_ST()  asm volatile("tcgen05.wait::st.sync.aligned;"  ::: "memory")
#define TC_FENCE_BEFORE() asm volatile("tcgen05.fence::before_thread_sync;" ::: "memory")
#define TC_FENCE_AFTER()  asm volatile("tcgen05.fence::after_thread_sync;"  ::: "memory")
#define FENCE_ASYNC_SHARED() asm volatile("fence.proxy.async.shared::cta;" ::: "memory")

#define CP_ASYNC16(dst, src) \
    asm volatile("cp.async.ca.shared.global [%0], [%1], 16;" \
                 :: "r"(dst), "l"(src) : "memory")
#define CP_COMMIT() asm volatile("cp.async.commit_group;" ::: "memory")
#define CP_WAIT0()  asm volatile("cp.async.wait_group 0;" ::: "memory")

#define LDTM_X32(r, addr) \
    asm volatile("tcgen05.ld.sync.aligned.32x32b.x32.b32 " \
        "{%0, %1, %2, %3, %4, %5, %6, %7, %8, %9, %10, %11, %12, %13, %14, %15, " \
        " %16, %17, %18, %19, %20, %21, %22, %23, %24, %25, %26, %27, %28, %29, %30, %31}, [%32];" \
        : "=r"((r)[0]),  "=r"((r)[1]),  "=r"((r)[2]),  "=r"((r)[3]),  \
          "=r"((r)[4]),  "=r"((r)[5]),  "=r"((r)[6]),  "=r"((r)[7]),  \
          "=r"((r)[8]),  "=r"((r)[9]),  "=r"((r)[10]), "=r"((r)[11]), \
          "=r"((r)[12]), "=r"((r)[13]), "=r"((r)[14]), "=r"((r)[15]), \
          "=r"((r)[16]), "=r"((r)[17]), "=r"((r)[18]), "=r"((r)[19]), \
          "=r"((r)[20]), "=r"((r)[21]), "=r"((r)[22]), "=r"((r)[23]), \
          "=r"((r)[24]), "=r"((r)[25]), "=r"((r)[26]), "=r"((r)[27]), \
          "=r"((r)[28]), "=r"((r)[29]), "=r"((r)[30]), "=r"((r)[31]) \
        : "r"(addr))

#define STTM_X16(addr, r) \
    asm volatile("tcgen05.st.sync.aligned.32x32b.x16.b32 [%0], " \
        "{%1, %2, %3, %4, %5, %6, %7, %8, %9, %10, %11, %12, %13, %14, %15, %16};" \
        :: "r"(addr), \
           "r"((r)[0]),  "r"((r)[1]),  "r"((r)[2]),  "r"((r)[3]),  \
           "r"((r)[4]),  "r"((r)[5]),  "r"((r)[6]),  "r"((r)[7]),  \
           "r"((r)[8]),  "r"((r)[9]),  "r"((r)[10]), "r"((r)[11]), \
           "r"((r)[12]), "r"((r)[13]), "r"((r)[14]), "r"((r)[15]) \
        : "memory")

__device__ __forceinline__ uint64_t make_desc(uint32_t smem_addr) {
    return 0x4000404000010000ULL | ((uint64_t)(smem_addr >> 4) & 0x3FFF);
}
__device__ __forceinline__ void mma_tf32_ss(uint32_t d, uint64_t a, uint64_t b,
                                            uint32_t idesc, uint32_t en) {
    asm volatile("{\n\t.reg .pred p;\n\tsetp.ne.u32 p, %5, 0;\n\t"
        "tcgen05.mma.cta_group::1.kind::tf32 [%0], %1, %2, %3, {%4, %4, %4, %4}, p;\n\t}"
        :: "r"(d), "l"(a), "l"(b), "r"(idesc), "r"(0u), "r"(en) : "memory");
}
__device__ __forceinline__ void mma_f16_ss(uint32_t d, uint64_t a, uint64_t b,
                                           uint32_t idesc, uint32_t en) {
    asm volatile("{\n\t.reg .pred p;\n\tsetp.ne.u32 p, %5, 0;\n\t"
        "tcgen05.mma.cta_group::1.kind::f16 [%0], %1, %2, %3, {%4, %4, %4, %4}, p;\n\t}"
        :: "r"(d), "l"(a), "l"(b), "r"(idesc), "r"(0u), "r"(en) : "memory");
}
__device__ __forceinline__ void mma_f16_ts(uint32_t d, uint32_t a, uint64_t b,
                                           uint32_t idesc, uint32_t en) {
    asm volatile("{\n\t.reg .pred p;\n\tsetp.ne.u32 p, %5, 0;\n\t"
        "tcgen05.mma.cta_group::1.kind::f16 [%0], [%1], %2, %3, {%4, %4, %4, %4}, p;\n\t}"
        :: "r"(d), "r"(a), "l"(b), "r"(idesc), "r"(0u), "r"(en) : "memory");
}
__device__ __forceinline__ uint32_t sw128(uint32_t b) { return b ^ ((b >> 3) & 0x70); }
#endif  // TC_OK

// ============================================================================
// tcgen05 QKV projection (UNCHANGED from R14 pass; fp16 outputs).
// ============================================================================
#define PSM_X   0
#define PSM_W   131072
#define PSM_PTR 196608
#define PSM_MB  196616
#define PROJ_SMEM 196640
#define IDESC_P ((1u << 4) | (2u << 7) | (2u << 10) | (4u << 17) | (8u << 24))

__global__ __launch_bounds__(256, 1) void proj_tc_kernel(
    const float* __restrict__ x,
    const float* __restrict__ Wq, const float* __restrict__ bq,
    const float* __restrict__ Wk, const float* __restrict__ bk,
    const float* __restrict__ Wv, const float* __restrict__ bv)
{
#if TC_OK
    extern __shared__ char sm[];
    const uint32_t smb = smem_u32(sm);
    const int tid = threadIdx.x;
    const int wid = tid >> 5;
    const int sp  = wid & 3;
    const int wg  = wid >> 2;
    const int lid = tid & 31;
    const int n0  = blockIdx.x * 128;
    const int b   = blockIdx.y;

    if (wid == 0) {
        TC_ALLOC(smb + PSM_PTR, 512);
        TC_RELINQ();
        if (elect_one()) {
            MBAR_INIT(smb + PSM_MB + 0, 1);
            MBAR_INIT(smb + PSM_MB + 8, 1);
        }
    }
    __syncthreads();
    uint32_t tmem;
    asm volatile("ld.shared.b32 %0, [%1];" : "=r"(tmem) : "r"(smb + PSM_PTR));
    const uint32_t woff = (uint32_t)sp << 21;
    const int n = sp * 32 + lid;

    {
        const float* xb = x + (size_t)b * EMB * NTOK + n0;
        #pragma unroll 8
        for (int it = 0; it < 32; ++it) {
            const int idx = tid + it * 256;
            const int c   = idx >> 5;
            const int nc4 = idx & 31;
            float4 v = *(const float4*)&xb[(size_t)c * NTOK + nc4 * 4];
            const uint32_t cb = (uint32_t)((c >> 5) * 16384 + ((c >> 2) & 7) * 16 + (c & 3) * 4);
            #pragma unroll
            for (int k2 = 0; k2 < 4; ++k2) {
                const int nn = nc4 * 4 + k2;
                uint32_t byte = cb + (uint32_t)((nn >> 3) * 1024 + (nn & 7) * 128);
                *(float*)(sm + PSM_X + sw128(byte)) =
                    f2tf32(k2 == 0 ? v.x : k2 == 1 ? v.y : k2 == 2 ? v.z : v.w);
            }
        }
    }

    const uint64_t xdesc = make_desc(smb + PSM_X);
    const float* Ws[3] = { Wq, Wk, Wv };
    int php[2] = { 0, 0 };

    for (int i = 0; i < 24; ++i) {
        const int bi = i & 1;
        if (i >= 2) { MBAR_WAIT(smb + PSM_MB + bi * 8, php[bi]); php[bi] ^= 1; }

        if (i == 16) {
            TC_FENCE_AFTER();
            const float scl = 0.0625f * LOG2E;
            __half* dst0 = g_q + ((size_t)b * NTOK + n0 + n) * EMB;
            #pragma unroll
            for (int cc = 0; cc < 4; ++cc) {
                const int col0 = wg * 128 + cc * 32;
                uint32_t r[32];
                LDTM_X32(r, tmem + (uint32_t)col0 + woff);
                TC_WAIT_LD();
                #pragma unroll
                for (int j = 0; j < 32; j += 8) {
                    uint32_t w[4];
                    #pragma unroll
                    for (int k2 = 0; k2 < 4; ++k2) {
                        const float v0 = (__uint_as_float(r[j+2*k2+0]) + __ldg(&bq[col0+j+2*k2+0])) * scl;
                        const float v1 = (__uint_as_float(r[j+2*k2+1]) + __ldg(&bq[col0+j+2*k2+1])) * scl;
                        asm("cvt.rn.f16x2.f32 %0, %1, %2;" : "=r"(w[k2]) : "f"(v1), "f"(v0));
                    }
                    uint4 o; o.x = w[0]; o.y = w[1]; o.z = w[2]; o.w = w[3];
                    *(uint4*)&dst0[col0 + j] = o;
                }
            }
            TC_FENCE_BEFORE();
            __syncthreads();
        }

        {
            const float* W = Ws[i >> 3] + (size_t)((i & 7) * 32) * EMB;
            char* buf = sm + PSM_W + bi * 32768;
            #pragma unroll
            for (int it = 0; it < 8; ++it) {
                const int idx = tid + it * 256;
                const int r  = idx >> 6;
                const int c4 = idx & 63;
                float4 v = *(const float4*)&W[(size_t)r * EMB + c4 * 4];
                v.x = f2tf32(v.x); v.y = f2tf32(v.y);
                v.z = f2tf32(v.z); v.w = f2tf32(v.w);
                uint32_t byte = (uint32_t)(((r >> 3) + (c4 >> 3) * 4) * 1024
                                           + (r & 7) * 128 + (c4 & 7) * 16);
                *(float4*)(buf + sw128(byte)) = v;
            }
        }
        FENCE_ASYNC_SHARED();
        __syncthreads();

        if (wid == 0) {
            TC_FENCE_AFTER();
            if (elect_one()) {
                const uint64_t wd = make_desc(smb + PSM_W + (uint32_t)(bi * 32768));
                const uint32_t dtm = tmem + (uint32_t)(((i >> 3) == 1 ? 256 : 0) + (i & 7) * 32);
                #pragma unroll
                for (int s = 0; s < 32; ++s) {
                    mma_tf32_ss(dtm, xdesc + (uint64_t)((s >> 2) * 1024 + (s & 3) * 2),
                                     wd    + (uint64_t)((s >> 2) * 256  + (s & 3) * 2),
                                IDESC_P, (uint32_t)(s > 0));
                }
                TC_COMMIT(smb + PSM_MB + bi * 8);
            }
        }
    }
    MBAR_WAIT(smb + PSM_MB + 0, php[0]); php[0] ^= 1;
    MBAR_WAIT(smb + PSM_MB + 8, php[1]); php[1] ^= 1;
    TC_FENCE_AFTER();

    {
        __half* dst = g_k + ((size_t)b * NTOK + n0 + n) * EMB;
        #pragma unroll
        for (int cc = 0; cc < 4; ++cc) {
            const int col0 = wg * 128 + cc * 32;
            uint32_t r[32];
            LDTM_X32(r, tmem + (uint32_t)(256 + col0) + woff);
            TC_WAIT_LD();
            #pragma unroll
            for (int j = 0; j < 32; j += 8) {
                uint32_t w[4];
                #pragma unroll
                for (int k2 = 0; k2 < 4; ++k2) {
                    const float v0 = __uint_as_float(r[j+2*k2+0]) + __ldg(&bk[col0+j+2*k2+0]);
                    const float v1 = __uint_as_float(r[j+2*k2+1]) + __ldg(&bk[col0+j+2*k2+1]);
                    asm("cvt.rn.f16x2.f32 %0, %1, %2;" : "=r"(w[k2]) : "f"(v1), "f"(v0));
                }
                uint4 o; o.x = w[0]; o.y = w[1]; o.z = w[2]; o.w = w[3];
                *(uint4*)&dst[col0 + j] = o;
            }
        }
    }
    {
        __half* vt = g_vt + (size_t)b * EMB * NTOK + n0 + n;
        #pragma unroll
        for (int cc = 0; cc < 4; ++cc) {
            const int col0 = wg * 128 + cc * 32;
            uint32_t r[32];
            LDTM_X32(r, tmem + (uint32_t)col0 + woff);
            TC_WAIT_LD();
            #pragma unroll
            for (int j = 0; j < 32; ++j) {
                const float v = __uint_as_float(r[j]) + __ldg(&bv[col0 + j]);
                vt[(size_t)(col0 + j) * NTOK] = __float2half(v);
            }
        }
    }
    __syncthreads();
    if (wid == 0) {
        if (elect_one()) { MBAR_INVAL(smb + PSM_MB + 0); MBAR_INVAL(smb + PSM_MB + 8); }
        TC_DEALLOC(tmem, 512);
    }
#endif
}

// ============================================================================
// fp16 tcgen05 attention v7 (R14 base; V load hoisted above softmax so its
// latency hides under exp/pack; K and V in separate cp.async groups).
// CTA = (128 q, batch), 512 threads. SMEM: Q 64K + K 64K + V 64K.
// TMEM: S@0 (128 fp32), P0@128, P1@192 (f16x2), O@256 (256 fp32).
// Iter: wait mb1(n) -> cp.K(n+1) -> LDTM S -> wait(K) -> sync -> issue MMA1(n+1)
//       -> wait mb2(n-1) -> cp.V(n) -> softmax/pack (V in flight)
//       -> STTM P[n&1] -> wait(V) -> sync -> issue MMA2(n).
// ============================================================================
#define SM_Q   0
#define SM_K   65536
#define SM_V   131072
#define SM_PTR 196608
#define SM_M1  196616
#define SM_M2  196624
#define SM_L   196640
#define ATT_SMEM (196640 + 4 * 128 * 4)
#define TM_S 0
#define TM_P 128
#define TM_O 256
#define IDESC1 ((1u << 4) | (16u << 17) | (8u << 24))
#define IDESC2 ((1u << 4) | (32u << 17) | (8u << 24))

#if TC_OK
__device__ __forceinline__ void load_qk_tile(char* dst, const __half* g, int tid) {
    #pragma unroll 8
    for (int it = 0; it < 8; ++it) {
        const int idx = tid + it * 512;
        const int r = idx >> 5;
        const int c = idx & 31;
        uint4 v = *(const uint4*)&g[(size_t)r * EMB + c * 8];
        uint32_t byte = (uint32_t)(((r >> 3) + (c >> 3) * 16) * 1024
                                   + (r & 7) * 128 + (c & 7) * 16);
        *(uint4*)(dst + sw128(byte)) = v;
    }
}
__device__ __forceinline__ void cp_k_tile(uint32_t dst, const __half* g, int tid) {
    #pragma unroll
    for (int it = 0; it < 8; ++it) {
        const int idx = tid + it * 512;
        const int r = idx >> 5;
        const int c = idx & 31;
        uint32_t byte = (uint32_t)(((r >> 3) + (c >> 3) * 16) * 1024
                                   + (r & 7) * 128 + (c & 7) * 16);
        CP_ASYNC16(dst + sw128(byte), (const char*)(g + (size_t)r * EMB + c * 8));
    }
}
__device__ __forceinline__ void cp_v_tile(uint32_t dst, const __half* g, int tid) {
    #pragma unroll
    for (int it = 0; it < 8; ++it) {
        const int idx = tid + it * 512;
        const int r = idx >> 4;
        const int c = idx & 15;
        uint32_t byte = (uint32_t)(((r >> 3) + (c >> 3) * 32) * 1024
                                   + (r & 7) * 128 + (c & 7) * 16);
        CP_ASYNC16(dst + sw128(byte), (const char*)(g + (size_t)r * NTOK + c * 8));
    }
}
__device__ __forceinline__ void issue_mma1(uint32_t sdst, uint64_t qdesc,
                                           uint64_t kdesc, uint32_t mbar) {
    #pragma unroll
    for (int s = 0; s < 16; ++s) {
        mma_f16_ss(sdst, qdesc + (uint64_t)((s >> 2) * 1024 + (s & 3) * 2),
                         kdesc + (uint64_t)((s >> 2) * 1024 + (s & 3) * 2),
                   IDESC1, (uint32_t)(s > 0));
    }
    TC_COMMIT(mbar);
}
#endif

__global__ __launch_bounds__(512, 1) void attn_tc_kernel(float* __restrict__ out)
{
#if TC_OK
    extern __shared__ char sm[];
    const uint32_t smb = smem_u32(sm);
    const int tid = threadIdx.x;
    const int wid = tid >> 5;
    const int sp  = wid & 3;
    const int wg  = wid >> 2;
    const int lid = tid & 31;
    const int q0  = blockIdx.x * 128;
    const int b   = blockIdx.y;

    if (wid == 0) {
        TC_ALLOC(smb + SM_PTR, 512);
        TC_RELINQ();
        if (elect_one()) { MBAR_INIT(smb + SM_M1, 1); MBAR_INIT(smb + SM_M2, 1); }
    }
    __syncthreads();
    uint32_t tmem;
    asm volatile("ld.shared.b32 %0, [%1];" : "=r"(tmem) : "r"(smb + SM_PTR));
    const uint32_t woff = (uint32_t)sp << 21;

    const uint64_t qdesc = make_desc(smb + SM_Q);
    const uint64_t kdesc = make_desc(smb + SM_K);
    const uint64_t vdesc = make_desc(smb + SM_V);

    const __half* gk = g_k + (size_t)b * NTOK * EMB;
    const __half* gv = g_vt + (size_t)b * EMB * NTOK;

    load_qk_tile(sm + SM_Q, g_q + ((size_t)b * NTOK + q0) * EMB, tid);
    load_qk_tile(sm + SM_K, gk, tid);
    FENCE_ASYNC_SHARED();
    __syncthreads();
    if (wid == 0) {
        TC_FENCE_AFTER();
        if (elect_one()) issue_mma1(tmem + TM_S, qdesc, kdesc, smb + SM_M1);
    }

    float lsum = 0.f;
    int ph1 = 0, ph2 = 0;

    for (int itn = 0; itn < NITER; ++itn) {
        const int k0 = itn * TCK;
        const uint32_t pbuf = TM_P + (uint32_t)((itn & 1) << 6);

        // (1) wait MMA1(n): S ready, K buffer free
        MBAR_WAIT(smb + SM_M1, ph1); ph1 ^= 1;
        TC_FENCE_AFTER();

        // (2) prefetch K(n+1) (own commit group; overlaps LDTM below)
        if (itn < NITER - 1) cp_k_tile(smb + SM_K, gk + (size_t)(k0 + TCK) * EMB, tid);
        CP_COMMIT();

        // (3) read S (frees S region)
        uint32_t sreg[32];
        LDTM_X32(sreg, tmem + TM_S + (uint32_t)(wg << 5) + woff);
        TC_WAIT_LD();

        // (4) K landed + S read by all -> issue MMA1(n+1)
        CP_WAIT0();
        FENCE_ASYNC_SHARED();
        __syncthreads();
        if (itn < NITER - 1 && wid == 0) {
            TC_FENCE_AFTER();
            if (elect_one()) issue_mma1(tmem + TM_S, qdesc, kdesc, smb + SM_M1);
        }

        // (5) wait MMA2(n-1) (had ~1 full iteration to finish); launch V(n)
        //     so its latency hides under the softmax below.
        if (itn > 0) { MBAR_WAIT(smb + SM_M2, ph2); ph2 ^= 1; }
        TC_FENCE_AFTER();
        cp_v_tile(smb + SM_V, gv + k0, tid);
        CP_COMMIT();

        // (6) softmax + pack (V in flight); store P[n&1] (free since MMA2(n-2))
        {
            uint32_t pr[16];
            float part = 0.f;
            #pragma unroll
            for (int j = 0; j < 16; ++j) {
                uint32_t h2;
                asm("cvt.rn.f16x2.f32 %0, %1, %2;" : "=r"(h2)
                    : "f"(__uint_as_float(sreg[2 * j + 1])),
                      "f"(__uint_as_float(sreg[2 * j])));
                asm("ex2.approx.f16x2 %0, %1;" : "=r"(pr[j]) : "r"(h2));
                const float2 f = __half22float2(*(__half2*)&pr[j]);
                part += f.x + f.y;
            }
            lsum += part;
            STTM_X16(tmem + pbuf + (uint32_t)(wg << 4) + woff, pr);
            TC_WAIT_ST();
        }
        TC_FENCE_BEFORE();

        // (7) V landed + all STTM done -> issue MMA2(n)
        CP_WAIT0();
        FENCE_ASYNC_SHARED();
        __syncthreads();
        if (wid == 0) {
            TC_FENCE_AFTER();
            if (elect_one()) {
                #pragma unroll
                for (int s = 0; s < 8; ++s) {
                    mma_f16_ts(tmem + TM_O, tmem + pbuf + s * 8,
                               vdesc + (uint64_t)((s >> 2) * 2048 + (s & 3) * 2),
                               IDESC2, (uint32_t)((itn > 0) | (s > 0)));
                }
                TC_COMMIT(smb + SM_M2);
            }
        }
    }

    // epilogue
    MBAR_WAIT(smb + SM_M2, ph2); ph2 ^= 1;
    TC_FENCE_AFTER();
    {
        float* lpart = (float*)(sm + SM_L);
        const int row = sp * 32 + lid;
        lpart[wg * 128 + row] = lsum;
        __syncthreads();
        const float inv = 1.f / (lpart[row] + lpart[128 + row]
                               + lpart[256 + row] + lpart[384 + row]);

        float* ob = out + ((size_t)b * NTOK + q0 + row) * EMB + wg * 64;
        #pragma unroll
        for (int ch = 0; ch < 2; ++ch) {
            uint32_t r[32];
            LDTM_X32(r, tmem + TM_O + (uint32_t)(wg * 64 + ch * 32) + woff);
            TC_WAIT_LD();
            #pragma unroll
            for (int j = 0; j < 32; j += 4) {
                float4 o;
                o.x = __uint_as_float(r[j + 0]) * inv;
                o.y = __uint_as_float(r[j + 1]) * inv;
                o.z = __uint_as_float(r[j + 2]) * inv;
                o.w = __uint_as_float(r[j + 3]) * inv;
                *(float4*)&ob[ch * 32 + j] = o;
            }
        }
    }
    __syncthreads();
    if (wid == 0) {
        if (elect_one()) { MBAR_INVAL(smb + SM_M1); MBAR_INVAL(smb + SM_M2); }
        TC_DEALLOC(tmem, 512);
    }
#endif
}

// ---------------------------------------------------------------------------
extern "C" void kernel_launch(void* const* d_in, const int* in_sizes, int n_in,
                              void* d_out, int out_size)
{
    const float* x  = (const float*)d_in[0];
    const float* Wq = (const float*)d_in[1];
    const float* bq = (const float*)d_in[2];
    const float* Wk = (const float*)d_in[3];
    const float* bk = (const float*)d_in[4];
    const float* Wv = (const float*)d_in[5];
    const float* bv = (const float*)d_in[6];
    float* out = (float*)d_out;

    cudaFuncSetAttribute(proj_tc_kernel,
                         cudaFuncAttributeMaxDynamicSharedMemorySize, PROJ_SMEM);
    cudaFuncSetAttribute(attn_tc_kernel,
                         cudaFuncAttributeMaxDynamicSharedMemorySize, ATT_SMEM);

    dim3 gproj(NTOK / 128, BATCH);
    proj_tc_kernel<<<gproj, 256, PROJ_SMEM>>>(x, Wq, bq, Wk, bk, Wv, bv);

    dim3 gatt(NTOK / 128, BATCH);
    attn_tc_kernel<<<gatt, 512, ATT_SMEM>>>(out);
}

// round 17
// speedup vs baseline: 1.2343x; 1.0868x over previous
#include <cuda_runtime.h>
#include <cuda_fp16.h>
#include <cstdint>

#define BATCH 4
#define EMB   256
#define NTOK  4096
#define TCK   128
#define NITER (NTOK / TCK)
#define LOG2E 1.4426950408889634f

__device__ __half g_q [(size_t)BATCH * NTOK * EMB];
__device__ __half g_k [(size_t)BATCH * NTOK * EMB];
__device__ __half g_vt[(size_t)BATCH * EMB * NTOK];

#if defined(__CUDA_ARCH_FEAT_SM103_ALL) || defined(__CUDA_ARCH_FEAT_SM100_ALL) || \
    defined(__CUDA_ARCH_FEAT_SM101_ALL) || defined(__CUDA_ARCH_SPECIFIC__)
#define TC_OK 1
#else
#define TC_OK 0
#endif

#if TC_OK
__device__ __forceinline__ uint32_t smem_u32(const void* p) {
    uint32_t a;
    asm("{ .reg .u64 t; cvta.to.shared.u64 t, %1; cvt.u32.u64 %0, t; }"
        : "=r"(a) : "l"(p));
    return a;
}
__device__ __forceinline__ uint32_t elect_one() {
    uint32_t pred;
    asm volatile("{\n\t.reg .pred p;\n\telect.sync _|p, 0xFFFFFFFF;\n\t"
                 "selp.b32 %0, 1, 0, p;\n\t}" : "=r"(pred));
    return pred;
}

#define MBAR_INIT(mbar, cnt) \
    asm volatile("mbarrier.init.shared.b64 [%0], %1;" :: "r"(mbar), "r"(cnt) : "memory")
#define MBAR_INVAL(mbar) \
    asm volatile("mbarrier.inval.shared.b64 [%0];" :: "r"(mbar) : "memory")
#define MBAR_WAIT(mbar, parity) do {                                             \
    uint32_t _mb = (mbar); uint32_t _ph = (parity); uint32_t _done;              \
    asm volatile("{\n\t.reg .pred p;\n\t"                                        \
        "mbarrier.try_wait.parity.acquire.cta.shared::cta.b64 p, [%1], %2;\n\t"  \
        "selp.b32 %0, 1, 0, p;\n\t}"                                             \
        : "=r"(_done) : "r"(_mb), "r"(_ph) : "memory");                          \
    if (!_done) {                                                                \
        asm volatile("{\n\t.reg .pred P1;\n\t"                                   \
            "WL_%=:\n\t"                                                         \
            "mbarrier.try_wait.parity.acquire.cta.shared::cta.b64 P1, [%0], %1, 0x989680;\n\t" \
            "@P1 bra.uni WD_%=;\n\t"                                             \
            "bra.uni WL_%=;\n\t"                                                 \
            "WD_%=:\n\t}" :: "r"(_mb), "r"(_ph) : "memory");                     \
    }                                                                            \
} while (0)

#define TC_ALLOC(dst_smem, ncols) \
    asm volatile("tcgen05.alloc.cta_group::1.sync.aligned.shared::cta.b32 [%0], %1;" \
                 :: "r"(dst_smem), "r"(ncols) : "memory")
#define TC_RELINQ() \
    asm volatile("tcgen05.relinquish_alloc_permit.cta_group::1.sync.aligned;")
#define TC_DEALLOC(tmem, ncols) \
    asm volatile("tcgen05.dealloc.cta_group::1.sync.aligned.b32 %0, %1;" \
                 :: "r"(tmem), "r"(ncols))
#define TC_COMMIT(mbar) \
    asm volatile("tcgen05.commit.cta_group::1.mbarrier::arrive::one.shared::cluster.b64 [%0];" \
                 :: "r"(mbar) : "memory")
#define TC_WAIT_LD()  asm volatile("tcgen05.wait::ld.sync.aligned;"  ::: "memory")
#define TC_WAIT_ST()  asm volatile("tcgen05.wait::st.sync.aligned;"  ::: "memory")
#define TC_FENCE_BEFORE() asm volatile("tcgen05.fence::before_thread_sync;" ::: "memory")
#define TC_FENCE_AFTER()  asm volatile("tcgen05.fence::after_thread_sync;"  ::: "memory")
#define FENCE_ASYNC_SHARED() asm volatile("fence.proxy.async.shared::cta;" ::: "memory")

#define CP_ASYNC16(dst, src) \
    asm volatile("cp.async.ca.shared.global [%0], [%1], 16;" \
                 :: "r"(dst), "l"(src) : "memory")
#define CP_COMMIT() asm volatile("cp.async.commit_group;" ::: "memory")
#define CP_WAIT0()  asm volatile("cp.async.wait_group 0;" ::: "memory")

#define LDTM_X32(r, addr) \
    asm volatile("tcgen05.ld.sync.aligned.32x32b.x32.b32 " \
        "{%0, %1, %2, %3, %4, %5, %6, %7, %8, %9, %10, %11, %12, %13, %14, %15, " \
        " %16, %17, %18, %19, %20, %21, %22, %23, %24, %25, %26, %27, %28, %29, %30, %31}, [%32];" \
        : "=r"((r)[0]),  "=r"((r)[1]),  "=r"((r)[2]),  "=r"((r)[3]),  \
          "=r"((r)[4]),  "=r"((r)[5]),  "=r"((r)[6]),  "=r"((r)[7]),  \
          "=r"((r)[8]),  "=r"((r)[9]),  "=r"((r)[10]), "=r"((r)[11]), \
          "=r"((r)[12]), "=r"((r)[13]), "=r"((r)[14]), "=r"((r)[15]), \
          "=r"((r)[16]), "=r"((r)[17]), "=r"((r)[18]), "=r"((r)[19]), \
          "=r"((r)[20]), "=r"((r)[21]), "=r"((r)[22]), "=r"((r)[23]), \
          "=r"((r)[24]), "=r"((r)[25]), "=r"((r)[26]), "=r"((r)[27]), \
          "=r"((r)[28]), "=r"((r)[29]), "=r"((r)[30]), "=r"((r)[31]) \
        : "r"(addr))

#define STTM_X16(addr, r) \
    asm volatile("tcgen05.st.sync.aligned.32x32b.x16.b32 [%0], " \
        "{%1, %2, %3, %4, %5, %6, %7, %8, %9, %10, %11, %12, %13, %14, %15, %16};" \
        :: "r"(addr), \
           "r"((r)[0]),  "r"((r)[1]),  "r"((r)[2]),  "r"((r)[3]),  \
           "r"((r)[4]),  "r"((r)[5]),  "r"((r)[6]),  "r"((r)[7]),  \
           "r"((r)[8]),  "r"((r)[9]),  "r"((r)[10]), "r"((r)[11]), \
           "r"((r)[12]), "r"((r)[13]), "r"((r)[14]), "r"((r)[15]) \
        : "memory")

__device__ __forceinline__ uint64_t make_desc(uint32_t smem_addr) {
    return 0x4000404000010000ULL | ((uint64_t)(smem_addr >> 4) & 0x3FFF);
}
__device__ __forceinline__ void mma_f16_ss(uint32_t d, uint64_t a, uint64_t b,
                                           uint32_t idesc, uint32_t en) {
    asm volatile("{\n\t.reg .pred p;\n\tsetp.ne.u32 p, %5, 0;\n\t"
        "tcgen05.mma.cta_group::1.kind::f16 [%0], %1, %2, %3, {%4, %4, %4, %4}, p;\n\t}"
        :: "r"(d), "l"(a), "l"(b), "r"(idesc), "r"(0u), "r"(en) : "memory");
}
__device__ __forceinline__ void mma_f16_ts(uint32_t d, uint32_t a, uint64_t b,
                                           uint32_t idesc, uint32_t en) {
    asm volatile("{\n\t.reg .pred p;\n\tsetp.ne.u32 p, %5, 0;\n\t"
        "tcgen05.mma.cta_group::1.kind::f16 [%0], [%1], %2, %3, {%4, %4, %4, %4}, p;\n\t}"
        :: "r"(d), "r"(a), "l"(b), "r"(idesc), "r"(0u), "r"(en) : "memory");
}
__device__ __forceinline__ uint32_t sw128(uint32_t b) { return b ^ ((b >> 3) & 0x70); }
#endif  // TC_OK

// ============================================================================
// tcgen05 QKV projection v2: fp16 MMA (X^T and W staged as fp16).
// CTA = (128-token tile, batch), 256 threads.
// SMEM: X^T [128n x 256c] f16 SW128 (16x4 atoms, 64KB) @0;
//       W chunks [32d x 256c] f16 (4x4 atoms, 16KB) double-buffered @65536.
// TMEM: D double-buffered (2 x 256 fp32 cols). 24 chunk-MMAs, 16 K-steps each.
// ============================================================================
#define PSM_X   0
#define PSM_W   65536
#define PSM_PTR 98304
#define PSM_MB  98312
#define PROJ_SMEM 98336
#define IDESC_PH ((1u << 4) | (4u << 17) | (8u << 24))   /* f16 in, f32 out, N=32, M=128 */

__global__ __launch_bounds__(256, 1) void proj_tc_kernel(
    const float* __restrict__ x,
    const float* __restrict__ Wq, const float* __restrict__ bq,
    const float* __restrict__ Wk, const float* __restrict__ bk,
    const float* __restrict__ Wv, const float* __restrict__ bv)
{
#if TC_OK
    extern __shared__ char sm[];
    const uint32_t smb = smem_u32(sm);
    const int tid = threadIdx.x;
    const int wid = tid >> 5;
    const int sp  = wid & 3;
    const int wg  = wid >> 2;
    const int lid = tid & 31;
    const int n0  = blockIdx.x * 128;
    const int b   = blockIdx.y;

    if (wid == 0) {
        TC_ALLOC(smb + PSM_PTR, 512);
        TC_RELINQ();
        if (elect_one()) {
            MBAR_INIT(smb + PSM_MB + 0, 1);
            MBAR_INIT(smb + PSM_MB + 8, 1);
        }
    }
    __syncthreads();
    uint32_t tmem;
    asm volatile("ld.shared.b32 %0, [%1];" : "=r"(tmem) : "r"(smb + PSM_PTR));
    const uint32_t woff = (uint32_t)sp << 21;
    const int n = sp * 32 + lid;

    // ---- X^T staging: read x[b][c][n0+4n..] fp32, store fp16 transposed ----
    // fp16 layout: byte(n,c) = ((n>>3) + (c>>6)*16)*1024 + (n&7)*128 + (c&63)*2
    {
        const float* xb = x + (size_t)b * EMB * NTOK + n0;
        #pragma unroll 8
        for (int it = 0; it < 32; ++it) {
            const int idx = tid + it * 256;
            const int c   = idx >> 5;
            const int nc4 = idx & 31;
            float4 v = *(const float4*)&xb[(size_t)c * NTOK + nc4 * 4];
            const uint32_t cb = (uint32_t)(((c >> 6) * 16) * 1024 + (c & 63) * 2);
            __half h[4];
            h[0] = __float2half(v.x); h[1] = __float2half(v.y);
            h[2] = __float2half(v.z); h[3] = __float2half(v.w);
            #pragma unroll
            for (int k2 = 0; k2 < 4; ++k2) {
                const int nn = nc4 * 4 + k2;
                uint32_t byte = cb + (uint32_t)((nn >> 3) * 1024 + (nn & 7) * 128);
                *(__half*)(sm + PSM_X + sw128(byte)) = h[k2];
            }
        }
    }

    const uint64_t xdesc = make_desc(smb + PSM_X);
    const float* Ws[3] = { Wq, Wk, Wv };
    int php[2] = { 0, 0 };

    for (int i = 0; i < 24; ++i) {
        const int bi = i & 1;
        if (i >= 2) { MBAR_WAIT(smb + PSM_MB + bi * 8, php[bi]); php[bi] ^= 1; }

        if (i == 16) {   // epilogue q (D buffer 0, cols 0..255): fp16 out, prescaled
            TC_FENCE_AFTER();
            const float scl = 0.0625f * LOG2E;
            __half* dst0 = g_q + ((size_t)b * NTOK + n0 + n) * EMB;
            #pragma unroll
            for (int cc = 0; cc < 4; ++cc) {
                const int col0 = wg * 128 + cc * 32;
                uint32_t r[32];
                LDTM_X32(r, tmem + (uint32_t)col0 + woff);
                TC_WAIT_LD();
                #pragma unroll
                for (int j = 0; j < 32; j += 8) {
                    uint32_t w[4];
                    #pragma unroll
                    for (int k2 = 0; k2 < 4; ++k2) {
                        const float v0 = (__uint_as_float(r[j+2*k2+0]) + __ldg(&bq[col0+j+2*k2+0])) * scl;
                        const float v1 = (__uint_as_float(r[j+2*k2+1]) + __ldg(&bq[col0+j+2*k2+1])) * scl;
                        asm("cvt.rn.f16x2.f32 %0, %1, %2;" : "=r"(w[k2]) : "f"(v1), "f"(v0));
                    }
                    uint4 o; o.x = w[0]; o.y = w[1]; o.z = w[2]; o.w = w[3];
                    *(uint4*)&dst0[col0 + j] = o;
                }
            }
            TC_FENCE_BEFORE();
            __syncthreads();
        }

        // ---- load W chunk i (32d x 256c) as fp16 into buffer bi ----
        // byte(d,c) = ((d>>3) + (c>>6)*4)*1024 + (d&7)*128 + (c&63)*2
        {
            const float* W = Ws[i >> 3] + (size_t)((i & 7) * 32) * EMB;
            char* buf = sm + PSM_W + bi * 16384;
            #pragma unroll
            for (int it = 0; it < 8; ++it) {
                const int idx = tid + it * 256;
                const int r  = idx >> 6;
                const int c4 = idx & 63;
                float4 v = *(const float4*)&W[(size_t)r * EMB + c4 * 4];
                uint32_t lo, hi;
                asm("cvt.rn.f16x2.f32 %0, %1, %2;" : "=r"(lo) : "f"(v.y), "f"(v.x));
                asm("cvt.rn.f16x2.f32 %0, %1, %2;" : "=r"(hi) : "f"(v.w), "f"(v.z));
                uint32_t byte = (uint32_t)(((r >> 3) + (c4 >> 4) * 4) * 1024
                                           + (r & 7) * 128 + (c4 & 15) * 8);
                uint2 o; o.x = lo; o.y = hi;
                *(uint2*)(buf + sw128(byte)) = o;
            }
        }
        FENCE_ASYNC_SHARED();
        __syncthreads();

        if (wid == 0) {
            TC_FENCE_AFTER();
            if (elect_one()) {
                const uint64_t wd = make_desc(smb + PSM_W + (uint32_t)(bi * 16384));
                const uint32_t dtm = tmem + (uint32_t)(((i >> 3) == 1 ? 256 : 0) + (i & 7) * 32);
                #pragma unroll
                for (int s = 0; s < 16; ++s) {
                    mma_f16_ss(dtm, xdesc + (uint64_t)((s >> 2) * 1024 + (s & 3) * 2),
                                    wd    + (uint64_t)((s >> 2) * 256  + (s & 3) * 2),
                               IDESC_PH, (uint32_t)(s > 0));
                }
                TC_COMMIT(smb + PSM_MB + bi * 8);
            }
        }
    }
    MBAR_WAIT(smb + PSM_MB + 0, php[0]); php[0] ^= 1;
    MBAR_WAIT(smb + PSM_MB + 8, php[1]); php[1] ^= 1;
    TC_FENCE_AFTER();

    // epilogue k (D cols 256..511) -> fp16 [n][d]
    {
        __half* dst = g_k + ((size_t)b * NTOK + n0 + n) * EMB;
        #pragma unroll
        for (int cc = 0; cc < 4; ++cc) {
            const int col0 = wg * 128 + cc * 32;
            uint32_t r[32];
            LDTM_X32(r, tmem + (uint32_t)(256 + col0) + woff);
            TC_WAIT_LD();
            #pragma unroll
            for (int j = 0; j < 32; j += 8) {
                uint32_t w[4];
                #pragma unroll
                for (int k2 = 0; k2 < 4; ++k2) {
                    const float v0 = __uint_as_float(r[j+2*k2+0]) + __ldg(&bk[col0+j+2*k2+0]);
                    const float v1 = __uint_as_float(r[j+2*k2+1]) + __ldg(&bk[col0+j+2*k2+1]);
                    asm("cvt.rn.f16x2.f32 %0, %1, %2;" : "=r"(w[k2]) : "f"(v1), "f"(v0));
                }
                uint4 o; o.x = w[0]; o.y = w[1]; o.z = w[2]; o.w = w[3];
                *(uint4*)&dst[col0 + j] = o;
            }
        }
    }
    // epilogue v -> g_vt[d][n] fp16 (coalesced over n within each warp)
    {
        __half* vt = g_vt + (size_t)b * EMB * NTOK + n0 + n;
        #pragma unroll
        for (int cc = 0; cc < 4; ++cc) {
            const int col0 = wg * 128 + cc * 32;
            uint32_t r[32];
            LDTM_X32(r, tmem + (uint32_t)col0 + woff);
            TC_WAIT_LD();
            #pragma unroll
            for (int j = 0; j < 32; ++j) {
                const float v = __uint_as_float(r[j]) + __ldg(&bv[col0 + j]);
                vt[(size_t)(col0 + j) * NTOK] = __float2half(v);
            }
        }
    }
    __syncthreads();
    if (wid == 0) {
        if (elect_one()) { MBAR_INVAL(smb + PSM_MB + 0); MBAR_INVAL(smb + PSM_MB + 8); }
        TC_DEALLOC(tmem, 512);
    }
#endif
}

// ============================================================================
// fp16 tcgen05 attention — EXACT R14 schedule (best: 104.4us).
// CTA = (128 q, batch), 512 threads. SMEM: Q 64K + K 64K + V 64K.
// TMEM: S@0 (128 fp32), P0@128, P1@192 (f16x2), O@256 (256 fp32).
// ============================================================================
#define SM_Q   0
#define SM_K   65536
#define SM_V   131072
#define SM_PTR 196608
#define SM_M1  196616
#define SM_M2  196624
#define SM_L   196640
#define ATT_SMEM (196640 + 4 * 128 * 4)
#define TM_S 0
#define TM_P 128
#define TM_O 256
#define IDESC1 ((1u << 4) | (16u << 17) | (8u << 24))
#define IDESC2 ((1u << 4) | (32u << 17) | (8u << 24))

#if TC_OK
__device__ __forceinline__ void load_qk_tile(char* dst, const __half* g, int tid) {
    #pragma unroll 8
    for (int it = 0; it < 8; ++it) {
        const int idx = tid + it * 512;
        const int r = idx >> 5;
        const int c = idx & 31;
        uint4 v = *(const uint4*)&g[(size_t)r * EMB + c * 8];
        uint32_t byte = (uint32_t)(((r >> 3) + (c >> 3) * 16) * 1024
                                   + (r & 7) * 128 + (c & 7) * 16);
        *(uint4*)(dst + sw128(byte)) = v;
    }
}
__device__ __forceinline__ void cp_k_tile(uint32_t dst, const __half* g, int tid) {
    #pragma unroll
    for (int it = 0; it < 8; ++it) {
        const int idx = tid + it * 512;
        const int r = idx >> 5;
        const int c = idx & 31;
        uint32_t byte = (uint32_t)(((r >> 3) + (c >> 3) * 16) * 1024
                                   + (r & 7) * 128 + (c & 7) * 16);
        CP_ASYNC16(dst + sw128(byte), (const char*)(g + (size_t)r * EMB + c * 8));
    }
}
__device__ __forceinline__ void cp_v_tile(uint32_t dst, const __half* g, int tid) {
    #pragma unroll
    for (int it = 0; it < 8; ++it) {
        const int idx = tid + it * 512;
        const int r = idx >> 4;
        const int c = idx & 15;
        uint32_t byte = (uint32_t)(((r >> 3) + (c >> 3) * 32) * 1024
                                   + (r & 7) * 128 + (c & 7) * 16);
        CP_ASYNC16(dst + sw128(byte), (const char*)(g + (size_t)r * NTOK + c * 8));
    }
}
__device__ __forceinline__ void issue_mma1(uint32_t sdst, uint64_t qdesc,
                                           uint64_t kdesc, uint32_t mbar) {
    #pragma unroll
    for (int s = 0; s < 16; ++s) {
        mma_f16_ss(sdst, qdesc + (uint64_t)((s >> 2) * 1024 + (s & 3) * 2),
                         kdesc + (uint64_t)((s >> 2) * 1024 + (s & 3) * 2),
                   IDESC1, (uint32_t)(s > 0));
    }
    TC_COMMIT(mbar);
}
#endif

__global__ __launch_bounds__(512, 1) void attn_tc_kernel(float* __restrict__ out)
{
#if TC_OK
    extern __shared__ char sm[];
    const uint32_t smb = smem_u32(sm);
    const int tid = threadIdx.x;
    const int wid = tid >> 5;
    const int sp  = wid & 3;
    const int wg  = wid >> 2;
    const int lid = tid & 31;
    const int q0  = blockIdx.x * 128;
    const int b   = blockIdx.y;

    if (wid == 0) {
        TC_ALLOC(smb + SM_PTR, 512);
        TC_RELINQ();
        if (elect_one()) { MBAR_INIT(smb + SM_M1, 1); MBAR_INIT(smb + SM_M2, 1); }
    }
    __syncthreads();
    uint32_t tmem;
    asm volatile("ld.shared.b32 %0, [%1];" : "=r"(tmem) : "r"(smb + SM_PTR));
    const uint32_t woff = (uint32_t)sp << 21;

    const uint64_t qdesc = make_desc(smb + SM_Q);
    const uint64_t kdesc = make_desc(smb + SM_K);
    const uint64_t vdesc = make_desc(smb + SM_V);

    const __half* gk = g_k + (size_t)b * NTOK * EMB;
    const __half* gv = g_vt + (size_t)b * EMB * NTOK;

    load_qk_tile(sm + SM_Q, g_q + ((size_t)b * NTOK + q0) * EMB, tid);
    load_qk_tile(sm + SM_K, gk, tid);
    FENCE_ASYNC_SHARED();
    __syncthreads();
    if (wid == 0) {
        TC_FENCE_AFTER();
        if (elect_one()) issue_mma1(tmem + TM_S, qdesc, kdesc, smb + SM_M1);
    }

    float lsum = 0.f;
    int ph1 = 0, ph2 = 0;

    for (int itn = 0; itn < NITER; ++itn) {
        const int k0 = itn * TCK;
        const uint32_t pbuf = TM_P + (uint32_t)((itn & 1) << 6);

        MBAR_WAIT(smb + SM_M1, ph1); ph1 ^= 1;
        TC_FENCE_AFTER();

        if (itn < NITER - 1) cp_k_tile(smb + SM_K, gk + (size_t)(k0 + TCK) * EMB, tid);
        CP_COMMIT();

        uint32_t sreg[32];
        LDTM_X32(sreg, tmem + TM_S + (uint32_t)(wg << 5) + woff);
        TC_WAIT_LD();

        CP_WAIT0();
        FENCE_ASYNC_SHARED();
        __syncthreads();
        if (itn < NITER - 1 && wid == 0) {
            TC_FENCE_AFTER();
            if (elect_one()) issue_mma1(tmem + TM_S, qdesc, kdesc, smb + SM_M1);
        }

        {
            uint32_t pr[16];
            float part = 0.f;
            #pragma unroll
            for (int j = 0; j < 16; ++j) {
                uint32_t h2;
                asm("cvt.rn.f16x2.f32 %0, %1, %2;" : "=r"(h2)
                    : "f"(__uint_as_float(sreg[2 * j + 1])),
                      "f"(__uint_as_float(sreg[2 * j])));
                asm("ex2.approx.f16x2 %0, %1;" : "=r"(pr[j]) : "r"(h2));
                const float2 f = __half22float2(*(__half2*)&pr[j]);
                part += f.x + f.y;
            }
            lsum += part;
            STTM_X16(tmem + pbuf + (uint32_t)(wg << 4) + woff, pr);
            TC_WAIT_ST();
        }
        TC_FENCE_BEFORE();

        if (itn > 0) { MBAR_WAIT(smb + SM_M2, ph2); ph2 ^= 1; }
        TC_FENCE_AFTER();
        cp_v_tile(smb + SM_V, gv + k0, tid);
        CP_COMMIT(); CP_WAIT0();
        FENCE_ASYNC_SHARED();
        __syncthreads();

        if (wid == 0) {
            TC_FENCE_AFTER();
            if (elect_one()) {
                #pragma unroll
                for (int s = 0; s < 8; ++s) {
                    mma_f16_ts(tmem + TM_O, tmem + pbuf + s * 8,
                               vdesc + (uint64_t)((s >> 2) * 2048 + (s & 3) * 2),
                               IDESC2, (uint32_t)((itn > 0) | (s > 0)));
                }
                TC_COMMIT(smb + SM_M2);
            }
        }
    }

    MBAR_WAIT(smb + SM_M2, ph2); ph2 ^= 1;
    TC_FENCE_AFTER();
    {
        float* lpart = (float*)(sm + SM_L);
        const int row = sp * 32 + lid;
        lpart[wg * 128 + row] = lsum;
        __syncthreads();
        const float inv = 1.f / (lpart[row] + lpart[128 + row]
                               + lpart[256 + row] + lpart[384 + row]);

        float* ob = out + ((size_t)b * NTOK + q0 + row) * EMB + wg * 64;
        #pragma unroll
        for (int ch = 0; ch < 2; ++ch) {
            uint32_t r[32];
            LDTM_X32(r, tmem + TM_O + (uint32_t)(wg * 64 + ch * 32) + woff);
            TC_WAIT_LD();
            #pragma unroll
            for (int j = 0; j < 32; j += 4) {
                float4 o;
                o.x = __uint_as_float(r[j + 0]) * inv;
                o.y = __uint_as_float(r[j + 1]) * inv;
                o.z = __uint_as_float(r[j + 2]) * inv;
                o.w = __uint_as_float(r[j + 3]) * inv;
                *(float4*)&ob[ch * 32 + j] = o;
            }
        }
    }
    __syncthreads();
    if (wid == 0) {
        if (elect_one()) { MBAR_INVAL(smb + SM_M1); MBAR_INVAL(smb + SM_M2); }
        TC_DEALLOC(tmem, 512);
    }
#endif
}

// ---------------------------------------------------------------------------
extern "C" void kernel_launch(void* const* d_in, const int* in_sizes, int n_in,
                              void* d_out, int out_size)
{
    const float* x  = (const float*)d_in[0];
    const float* Wq = (const float*)d_in[1];
    const float* bq = (const float*)d_in[2];
    const float* Wk = (const float*)d_in[3];
    const float* bk = (const float*)d_in[4];
    const float* Wv = (const float*)d_in[5];
    const float* bv = (const float*)d_in[6];
    float* out = (float*)d_out;

    cudaFuncSetAttribute(proj_tc_kernel,
                         cudaFuncAttributeMaxDynamicSharedMemorySize, PROJ_SMEM);
    cudaFuncSetAttribute(attn_tc_kernel,
                         cudaFuncAttributeMaxDynamicSharedMemorySize, ATT_SMEM);

    dim3 gproj(NTOK / 128, BATCH);
    proj_tc_kernel<<<gproj, 256, PROJ_SMEM>>>(x, Wq, bq, Wk, bk, Wv, bv);

    dim3 gatt(NTOK / 128, BATCH);
    attn_tc_kernel<<<gatt, 512, ATT_SMEM>>>(out);
}